// round 15
// baseline (speedup 1.0000x reference)
#include <cuda_runtime.h>
#include <stdint.h>

#define N_GRAPHS 1000
#define EPS 1e-5f
#define MAIN_THREADS 1024
#define MAIN_GRID 152   // = SM count; 1 block/SM; pinned L2 window 78MB < 126MB
#define FS_ELEMS 8      // batch elems per thread in the boundary prologue

__device__ int g_start[N_GRAPHS + 1];
__device__ unsigned int g_ready[N_GRAPHS + 1];  // generation-stamped readiness
__device__ unsigned int g_lc;                   // launch counter (monotonic)
__device__ unsigned int g_ticket;               // per-launch ticket (reset in epilogue)
__device__ unsigned int g_done;

// ---- L2 residency-hinted 128-bit loads via cache-policy descriptor --------
__device__ __forceinline__ unsigned long long mkpol_evict_last() {
    unsigned long long p;
    asm("createpolicy.fractional.L2::evict_last.b64 %0, 1.0;" : "=l"(p));
    return p;
}
__device__ __forceinline__ unsigned long long mkpol_evict_first() {
    unsigned long long p;
    asm("createpolicy.fractional.L2::evict_first.b64 %0, 1.0;" : "=l"(p));
    return p;
}
__device__ __forceinline__ float4 ldg_pol(const float4* p, unsigned long long pol) {
    float4 v;
    asm("ld.global.nc.L2::cache_hint.v4.f32 {%0,%1,%2,%3}, [%4], %5;"
        : "=f"(v.x), "=f"(v.y), "=f"(v.z), "=f"(v.w) : "l"(p), "l"(pol));
    return v;
}
__device__ __forceinline__ unsigned int ld_acq_u32(const unsigned int* p) {
    unsigned int v;
    asm volatile("ld.global.acquire.gpu.u32 %0, [%1];" : "=r"(v) : "l"(p));
    return v;
}
__device__ __forceinline__ void st_rel_u32(unsigned int* p, unsigned int v) {
    asm volatile("st.global.release.gpu.u32 [%0], %1;" :: "l"(p), "r"(v));
}
__device__ __forceinline__ int ld_cg_s32(const int* p) {
    int v;
    asm volatile("ld.global.cg.s32 %0, [%1];" : "=r"(v) : "l"(p));
    return v;
}

// ---------------------------------------------------------------------------
// Single persistent kernel:
//   Phase 0: cooperative boundary scan; each entry published with a
//            generation-stamped release flag (no device-wide barrier).
//   Phase 1: per-graph GraphNorm; tid0 acquires just the 2 flags it needs.
//   Epilogue: last block resets g_ticket/g_done (flags use generations).
// ---------------------------------------------------------------------------
__global__ __launch_bounds__(MAIN_THREADS, 1)
void graphnorm_fused_kernel(const float4* __restrict__ x,
                            const int*    __restrict__ batch,
                            const float*  __restrict__ nw,
                            const float*  __restrict__ weight,
                            const float*  __restrict__ bias,
                            const float*  __restrict__ msc,
                            float4* __restrict__ out,
                            int n) {
    __shared__ float s_sum [32][132];
    __shared__ float s_sum2[32][132];
    __shared__ float s_red1[8][128];
    __shared__ float s_red2[8][128];
    __shared__ float s_wp[32];
    __shared__ float s_wj[8];
    __shared__ float s_A[128];
    __shared__ float s_B[128];
    __shared__ int   s_g, s_start, s_end;
    __shared__ unsigned int s_gen;

    const int tid  = threadIdx.x;
    const int lane = tid & 31;
    const int grp  = tid >> 5;

    // ---- generation for this launch (each launch adds exactly MAIN_GRID) ----
    if (tid == 0) {
        unsigned int my = atomicAdd(&g_lc, 1u);
        s_gen = my / MAIN_GRID + 1u;            // same value for all 152 blocks
    }
    __syncthreads();
    const unsigned int gen = s_gen;

    // ================= Phase 0: boundary scan with release flags =================
    {
        const int gtid = blockIdx.x * MAIN_THREADS + tid;
        const int base = gtid * FS_ELEMS;
        if (base < n) {
            int pb = (base == 0) ? -1
                                 : min(max(__ldg(&batch[base - 1]), 0), N_GRAPHS - 1);
            #pragma unroll
            for (int q = 0; q < FS_ELEMS / 4; ++q) {
                int b0 = base + q * 4;
                if (b0 >= n) break;
                int v[4];
                if (b0 + 3 < n) {
                    int4 tt = __ldg((const int4*)(batch + b0));
                    v[0] = tt.x; v[1] = tt.y; v[2] = tt.z; v[3] = tt.w;
                } else {
                    for (int j = 0; j < 4; ++j)
                        v[j] = (b0 + j < n) ? __ldg(&batch[b0 + j]) : v[j > 0 ? j - 1 : 0];
                }
                for (int j = 0; j < 4; ++j) {
                    int idx = b0 + j;
                    if (idx >= n) break;
                    int b = min(max(v[j], 0), N_GRAPHS - 1);
                    for (int gg = pb + 1; gg <= b; ++gg) {
                        g_start[gg] = idx;
                        st_rel_u32(&g_ready[gg], gen);   // publish entry
                    }
                    if (idx == n - 1) {
                        for (int gg = b + 1; gg <= N_GRAPHS; ++gg) {
                            g_start[gg] = n;
                            st_rel_u32(&g_ready[gg], gen);
                        }
                    }
                    pb = b;
                }
            }
        }
    }
    // No barrier: consumers below acquire exactly the entries they need.

    // ================= Phase 1: GraphNorm =================
    const unsigned long long pol_last  = mkpol_evict_last();
    const unsigned long long pol_first = mkpol_evict_first();

    while (true) {
        if (tid == 0) {
            int t = (int)atomicAdd(&g_ticket, 1u);
            s_g = t;
            if (t < N_GRAPHS) {
                while (ld_acq_u32(&g_ready[t])     != gen) { }
                while (ld_acq_u32(&g_ready[t + 1]) != gen) { }
                s_start = ld_cg_s32(&g_start[t]);       // L1-bypass (fresh)
                s_end   = ld_cg_s32(&g_start[t + 1]);
            }
        }
        __syncthreads();
        const int g = s_g;
        if (g >= N_GRAPHS) break;
        const int start = s_start;
        const int end   = s_end;
        const int len   = end - start;

        // ---- Pass 1: weighted sums, forward order (pin lines in L2) ----
        float4 wx  = make_float4(0.f, 0.f, 0.f, 0.f);
        float4 wx2 = make_float4(0.f, 0.f, 0.f, 0.f);
        float  wa  = 0.f;
        #pragma unroll 4
        for (int r = start + grp; r < end; r += 32) {
            float  w = __ldg(&nw[r]);
            float4 v = ldg_pol(&x[(size_t)r * 32 + lane], pol_last);
            wa += w;
            wx.x += w * v.x;  wx.y += w * v.y;
            wx.z += w * v.z;  wx.w += w * v.w;
            wx2.x += w * v.x * v.x;  wx2.y += w * v.y * v.y;
            wx2.z += w * v.z * v.z;  wx2.w += w * v.w * v.w;
        }
        *(float4*)&s_sum [grp][4 * lane] = wx;
        *(float4*)&s_sum2[grp][4 * lane] = wx2;
        if (lane == 0) s_wp[grp] = wa;
        __syncthreads();

        // ---- Reduce stage A: 1024 threads, each sums 4 group-partials ----
        {
            const int ch = tid & 127;
            const int j  = tid >> 7;
            const int g0 = j * 4;
            s_red1[j][ch] = s_sum [g0][ch] + s_sum [g0+1][ch]
                          + s_sum [g0+2][ch] + s_sum [g0+3][ch];
            s_red2[j][ch] = s_sum2[g0][ch] + s_sum2[g0+1][ch]
                          + s_sum2[g0+2][ch] + s_sum2[g0+3][ch];
            if (tid < 8)
                s_wj[tid] = s_wp[tid*4] + s_wp[tid*4+1] + s_wp[tid*4+2] + s_wp[tid*4+3];
        }
        __syncthreads();

        // ---- Reduce stage B + coefficients: 128 threads ----
        if (tid < 128) {
            float swx = 0.f, swx2 = 0.f, sw = 0.f;
            #pragma unroll
            for (int j = 0; j < 8; ++j) {
                swx  += s_red1[j][tid];
                swx2 += s_red2[j][tid];
                sw   += s_wj[j];
            }
            float inv_w = 1.0f / fmaxf(sw, 1e-12f);
            float m  = swx  * inv_w;
            float m2 = swx2 * inv_w;
            float ms = __ldg(&msc[tid]);
            float wt = __ldg(&weight[tid]);
            float bs = __ldg(&bias[tid]);
            float var = m2 + m * m * ms * (ms - 2.f);
            float a = wt * rsqrtf(var + EPS);
            s_A[tid] = a;
            s_B[tid] = bs - m * ms * a;
        }
        __syncthreads();

        const float4 A = *(const float4*)&s_A[4 * lane];
        const float4 B = *(const float4*)&s_B[4 * lane];

        // ---- Pass 2: reverse order (most-recently-filled L2 lines first) ----
        if (grp < len) {
            const int rlo = start + grp;
            const int rhi = rlo + ((len - 1 - grp) / 32) * 32;
            #pragma unroll 4
            for (int r = rhi; r >= rlo; r -= 32) {
                float4 v = ldg_pol(&x[(size_t)r * 32 + lane], pol_first);
                float4 o;
                o.x = fmaf(A.x, v.x, B.x);
                o.y = fmaf(A.y, v.y, B.y);
                o.z = fmaf(A.z, v.z, B.z);
                o.w = fmaf(A.w, v.w, B.w);
                __stcs(&out[(size_t)r * 32 + lane], o);
            }
        }
        __syncthreads();
    }

    // ================= Epilogue: reset per-launch counters =================
    if (tid == 0) {
        __threadfence();
        unsigned int d = atomicAdd(&g_done, 1u);
        if (d == MAIN_GRID - 1) {
            g_ticket = 0;
            g_done   = 0;
            __threadfence();
        }
    }
}

// ---------------------------------------------------------------------------
// Launch: single persistent kernel.
// ---------------------------------------------------------------------------
extern "C" void kernel_launch(void* const* d_in, const int* in_sizes, int n_in,
                              void* d_out, int out_size) {
    const float* x      = (const float*)d_in[0];
    const int*   batch  = (const int*)d_in[1];     // int32 (JAX x64 disabled)
    const float* nw     = (const float*)d_in[2];
    const float* weight = (const float*)d_in[3];
    const float* bias   = (const float*)d_in[4];
    const float* msc    = (const float*)d_in[5];
    float* out = (float*)d_out;

    const int n = in_sizes[1];

    graphnorm_fused_kernel<<<MAIN_GRID, MAIN_THREADS>>>(
        (const float4*)x, batch, nw, weight, bias, msc, (float4*)out, n);
}

// round 16
// speedup vs baseline: 1.0137x; 1.0137x over previous
#include <cuda_runtime.h>
#include <stdint.h>

#define N_GRAPHS 1000
#define EPS 1e-5f
#define MAIN_THREADS 1024
#define MAIN_GRID 152   // = SM count; 1 block/SM guarantees co-residency (safe spin barrier)
#define FS_ELEMS 8      // batch elems per thread in the boundary prologue

__device__ int g_start[N_GRAPHS + 1];
__device__ unsigned int g_ticket;   // zero-init at module load; reset by epilogue
__device__ unsigned int g_arrive;
__device__ unsigned int g_done;

// ---- L2 residency-hinted 128-bit loads via cache-policy descriptor --------
__device__ __forceinline__ unsigned long long mkpol_evict_last() {
    unsigned long long p;
    asm("createpolicy.fractional.L2::evict_last.b64 %0, 1.0;" : "=l"(p));
    return p;
}
__device__ __forceinline__ unsigned long long mkpol_evict_first() {
    unsigned long long p;
    asm("createpolicy.fractional.L2::evict_first.b64 %0, 1.0;" : "=l"(p));
    return p;
}
__device__ __forceinline__ float4 ldg_pol(const float4* p, unsigned long long pol) {
    float4 v;
    asm("ld.global.nc.L2::cache_hint.v4.f32 {%0,%1,%2,%3}, [%4], %5;"
        : "=f"(v.x), "=f"(v.y), "=f"(v.z), "=f"(v.w) : "l"(p), "l"(pol));
    return v;
}
__device__ __forceinline__ unsigned int ld_acq_u32(const unsigned int* p) {
    unsigned int v;
    asm volatile("ld.global.acquire.gpu.u32 %0, [%1];" : "=r"(v) : "l"(p));
    return v;
}

// ---------------------------------------------------------------------------
// Single persistent kernel (R14 champion + ticket prefetch):
//   Phase 0: cooperative segment-boundary computation + device-wide barrier.
//   Phase 1: per-graph GraphNorm; the NEXT ticket + boundaries are fetched by
//            tid0 during pass 1, hiding the atomic/boundary latency.
//   Epilogue: last block resets scheduler globals for the next graph replay.
// ---------------------------------------------------------------------------
__global__ __launch_bounds__(MAIN_THREADS, 1)
void graphnorm_fused_kernel(const float4* __restrict__ x,
                            const int*    __restrict__ batch,
                            const float*  __restrict__ nw,
                            const float*  __restrict__ weight,
                            const float*  __restrict__ bias,
                            const float*  __restrict__ msc,
                            float4* __restrict__ out,
                            int n) {
    __shared__ float s_sum [32][132];
    __shared__ float s_sum2[32][132];
    __shared__ float s_red1[8][128];
    __shared__ float s_red2[8][128];
    __shared__ float s_wp[32];
    __shared__ float s_wj[8];
    __shared__ float s_A[128];
    __shared__ float s_B[128];
    __shared__ int   s_g, s_start, s_end;

    const int tid  = threadIdx.x;
    const int lane = tid & 31;
    const int grp  = tid >> 5;

    // ================= Phase 0: segment boundaries =================
    {
        const int gtid = blockIdx.x * MAIN_THREADS + tid;
        const int base = gtid * FS_ELEMS;
        if (base < n) {
            int pb = (base == 0) ? -1
                                 : min(max(__ldg(&batch[base - 1]), 0), N_GRAPHS - 1);
            #pragma unroll
            for (int q = 0; q < FS_ELEMS / 4; ++q) {
                int b0 = base + q * 4;
                if (b0 >= n) break;
                int v[4];
                if (b0 + 3 < n) {
                    int4 tt = __ldg((const int4*)(batch + b0));
                    v[0] = tt.x; v[1] = tt.y; v[2] = tt.z; v[3] = tt.w;
                } else {
                    for (int j = 0; j < 4; ++j)
                        v[j] = (b0 + j < n) ? __ldg(&batch[b0 + j]) : v[j > 0 ? j - 1 : 0];
                }
                for (int j = 0; j < 4; ++j) {
                    int idx = b0 + j;
                    if (idx >= n) break;
                    int b = min(max(v[j], 0), N_GRAPHS - 1);
                    for (int gg = pb + 1; gg <= b; ++gg) g_start[gg] = idx;
                    if (idx == n - 1) {
                        for (int gg = b + 1; gg <= N_GRAPHS; ++gg) g_start[gg] = n;
                    }
                    pb = b;
                }
            }
        }
        __syncthreads();
        if (tid == 0) {
            __threadfence();                       // publish g_start
            atomicAdd(&g_arrive, 1u);
            while (ld_acq_u32(&g_arrive) < MAIN_GRID) { /* spin */ }
        }
        __syncthreads();                           // whole block released
    }

    // ================= Phase 1: GraphNorm with prefetched tickets =================
    const unsigned long long pol_last  = mkpol_evict_last();
    const unsigned long long pol_first = mkpol_evict_first();

    // Fetch the first ticket.
    if (tid == 0) {
        int t = (int)atomicAdd(&g_ticket, 1u);
        s_g = t;
        if (t < N_GRAPHS) { s_start = g_start[t]; s_end = g_start[t + 1]; }
    }
    __syncthreads();
    int g = s_g, start = s_start, end = s_end;

    while (g < N_GRAPHS) {
        __syncthreads();        // everyone has copied s_* to regs; safe to overwrite

        // Prefetch NEXT ticket + boundaries; latency hides behind pass 1.
        if (tid == 0) {
            int t = (int)atomicAdd(&g_ticket, 1u);
            s_g = t;
            if (t < N_GRAPHS) { s_start = g_start[t]; s_end = g_start[t + 1]; }
        }

        const int len = end - start;

        // ---- Pass 1: weighted sums, forward order (pin lines in L2) ----
        float4 wx  = make_float4(0.f, 0.f, 0.f, 0.f);
        float4 wx2 = make_float4(0.f, 0.f, 0.f, 0.f);
        float  wa  = 0.f;
        #pragma unroll 4
        for (int r = start + grp; r < end; r += 32) {
            float  w = __ldg(&nw[r]);
            float4 v = ldg_pol(&x[(size_t)r * 32 + lane], pol_last);
            wa += w;
            wx.x += w * v.x;  wx.y += w * v.y;
            wx.z += w * v.z;  wx.w += w * v.w;
            wx2.x += w * v.x * v.x;  wx2.y += w * v.y * v.y;
            wx2.z += w * v.z * v.z;  wx2.w += w * v.w * v.w;
        }
        *(float4*)&s_sum [grp][4 * lane] = wx;
        *(float4*)&s_sum2[grp][4 * lane] = wx2;
        if (lane == 0) s_wp[grp] = wa;
        __syncthreads();

        // ---- Reduce stage A: 1024 threads, each sums 4 group-partials ----
        {
            const int ch = tid & 127;
            const int j  = tid >> 7;
            const int g0 = j * 4;
            s_red1[j][ch] = s_sum [g0][ch] + s_sum [g0+1][ch]
                          + s_sum [g0+2][ch] + s_sum [g0+3][ch];
            s_red2[j][ch] = s_sum2[g0][ch] + s_sum2[g0+1][ch]
                          + s_sum2[g0+2][ch] + s_sum2[g0+3][ch];
            if (tid < 8)
                s_wj[tid] = s_wp[tid*4] + s_wp[tid*4+1] + s_wp[tid*4+2] + s_wp[tid*4+3];
        }
        __syncthreads();

        // ---- Reduce stage B + coefficients: 128 threads ----
        if (tid < 128) {
            float swx = 0.f, swx2 = 0.f, sw = 0.f;
            #pragma unroll
            for (int j = 0; j < 8; ++j) {
                swx  += s_red1[j][tid];
                swx2 += s_red2[j][tid];
                sw   += s_wj[j];
            }
            float inv_w = 1.0f / fmaxf(sw, 1e-12f);
            float m  = swx  * inv_w;
            float m2 = swx2 * inv_w;
            float ms = __ldg(&msc[tid]);
            float wt = __ldg(&weight[tid]);
            float bs = __ldg(&bias[tid]);
            float var = m2 + m * m * ms * (ms - 2.f);
            float a = wt * rsqrtf(var + EPS);
            s_A[tid] = a;
            s_B[tid] = bs - m * ms * a;
        }
        __syncthreads();

        const float4 A = *(const float4*)&s_A[4 * lane];
        const float4 B = *(const float4*)&s_B[4 * lane];

        // ---- Pass 2: reverse order (most-recently-filled L2 lines first) ----
        if (grp < len) {
            const int rlo = start + grp;
            const int rhi = rlo + ((len - 1 - grp) / 32) * 32;
            #pragma unroll 4
            for (int r = rhi; r >= rlo; r -= 32) {
                float4 v = ldg_pol(&x[(size_t)r * 32 + lane], pol_first);
                float4 o;
                o.x = fmaf(A.x, v.x, B.x);
                o.y = fmaf(A.y, v.y, B.y);
                o.z = fmaf(A.z, v.z, B.z);
                o.w = fmaf(A.w, v.w, B.w);
                __stcs(&out[(size_t)r * 32 + lane], o);
            }
        }
        __syncthreads();        // tid0's prefetched s_* now stable & visible

        g = s_g; start = s_start; end = s_end;
    }

    // ================= Epilogue: reset globals for next replay =================
    if (tid == 0) {
        __threadfence();
        unsigned int d = atomicAdd(&g_done, 1u);
        if (d == MAIN_GRID - 1) {                 // last block out resets everything
            g_ticket = 0;
            g_arrive = 0;
            g_done   = 0;
            __threadfence();
        }
    }
}

// ---------------------------------------------------------------------------
// Launch: single persistent kernel.
// ---------------------------------------------------------------------------
extern "C" void kernel_launch(void* const* d_in, const int* in_sizes, int n_in,
                              void* d_out, int out_size) {
    const float* x      = (const float*)d_in[0];
    const int*   batch  = (const int*)d_in[1];     // int32 (JAX x64 disabled)
    const float* nw     = (const float*)d_in[2];
    const float* weight = (const float*)d_in[3];
    const float* bias   = (const float*)d_in[4];
    const float* msc    = (const float*)d_in[5];
    float* out = (float*)d_out;

    const int n = in_sizes[1];

    graphnorm_fused_kernel<<<MAIN_GRID, MAIN_THREADS>>>(
        (const float4*)x, batch, nw, weight, bias, msc, (float4*)out, n);
}